// round 14
// baseline (speedup 1.0000x reference)
#include <cuda_runtime.h>
#include <cuda_fp16.h>

#define OUT_DIM 11008
#define IN_DIM  4096
#define MTOK    2048

// ---------------- scratch (device globals; no runtime allocation) ----------------
__device__ __half g_Wh[(size_t)OUT_DIM * IN_DIM];
__device__ __half g_Xh[(size_t)MTOK * IN_DIM];
__device__ int    g_rowstart[OUT_DIM + 1];

static __device__ __forceinline__ unsigned smem_u32(const void* p) {
    return (unsigned)__cvta_generic_to_shared(p);
}

static __device__ __forceinline__ unsigned h2_as_u32(__half2 h) {
    return *reinterpret_cast<unsigned*>(&h);
}

#define CP16(dst_u32, src_ptr) \
    asm volatile("cp.async.cg.shared.global [%0], [%1], 16;" \
                 :: "r"(dst_u32), "l"(src_ptr) : "memory")

#define LDSM4(R, ADDR) \
    asm volatile("ldmatrix.sync.aligned.m8n8.x4.shared.b16 {%0,%1,%2,%3}, [%4];" \
                 : "=r"((R)[0]), "=r"((R)[1]), "=r"((R)[2]), "=r"((R)[3]) : "r"(ADDR))

#define MMA16816(C, A, B0, B1) \
    asm volatile("mma.sync.aligned.m16n8k16.row.col.f32.f16.f16.f32 " \
                 "{%0,%1,%2,%3}, {%4,%5,%6,%7}, {%8,%9}, {%0,%1,%2,%3};" \
                 : "+f"((C)[0]), "+f"((C)[1]), "+f"((C)[2]), "+f"((C)[3]) \
                 : "r"((A)[0]), "r"((A)[1]), "r"((A)[2]), "r"((A)[3]), \
                   "r"(B0), "r"(B1))

// ---------------- kernel 0: rowstart boundary scatter + x convert ----------------
// Blocks [0, RS_BLKS): boundary scatter over sorted rows.
// Blocks [RS_BLKS, RS_BLKS + XBLKS): convert x fp32 -> fp16.
#define XBLKS 2048   // 2048 blocks * 512 units = 1048576 = MTOK*IN_DIM/8

__global__ void __launch_bounds__(256) prep0_kernel(const int* __restrict__ rows,
                                                    int nnz, int rs_blks,
                                                    const float* __restrict__ x) {
    const int bid = blockIdx.x;
    if (bid < rs_blks) {
        int i = bid * 256 + threadIdx.x;
        if (i >= nnz) return;
        int r  = rows[i];
        int rp = (i == 0) ? -1 : rows[i - 1];
        for (int q = rp + 1; q <= r; ++q) g_rowstart[q] = i;
        if (i == nnz - 1)
            for (int q = r + 1; q <= OUT_DIM; ++q) g_rowstart[q] = nnz;
    } else {
        // two independent 8-elem units per thread; all 4 loads in flight first
        size_t u0 = (size_t)(bid - rs_blks) * 512 + threadIdx.x;
        size_t u1 = u0 + 256;
        float4 a0 = reinterpret_cast<const float4*>(x)[2 * u0 + 0];
        float4 a1 = reinterpret_cast<const float4*>(x)[2 * u0 + 1];
        float4 b0 = reinterpret_cast<const float4*>(x)[2 * u1 + 0];
        float4 b1 = reinterpret_cast<const float4*>(x)[2 * u1 + 1];
        uint4 oa, ob;
        oa.x = h2_as_u32(__floats2half2_rn(a0.x, a0.y));
        oa.y = h2_as_u32(__floats2half2_rn(a0.z, a0.w));
        oa.z = h2_as_u32(__floats2half2_rn(a1.x, a1.y));
        oa.w = h2_as_u32(__floats2half2_rn(a1.z, a1.w));
        ob.x = h2_as_u32(__floats2half2_rn(b0.x, b0.y));
        ob.y = h2_as_u32(__floats2half2_rn(b0.z, b0.w));
        ob.z = h2_as_u32(__floats2half2_rn(b1.x, b1.y));
        ob.w = h2_as_u32(__floats2half2_rn(b1.z, b1.w));
        reinterpret_cast<uint4*>(g_Xh)[u0] = oa;
        reinterpret_cast<uint4*>(g_Xh)[u1] = ob;
    }
}

// ---------------- fused W prep kernel: 2 rows per block ----------------
// Dequant 2 rows into fp32 smem, apply each row's sparse entries (ranges from
// g_rowstart, smem fp32 atomics), write both rows out once as fp16.
__global__ void __launch_bounds__(256) prep_kernel(
        const int* __restrict__ packed, const float* __restrict__ scales,
        const float* __restrict__ vals, const int* __restrict__ cols) {
    __shared__ float wsm[2 * IN_DIM];
    const int row0 = blockIdx.x * 2;
    const int tid  = threadIdx.x;
    const float s0 = scales[row0];
    const float s1 = scales[row0 + 1];
    const uint4* prow = reinterpret_cast<const uint4*>(packed) + (size_t)row0 * 512;

    #pragma unroll
    for (int u0 = 0; u0 < 4; ++u0) {
        int u = tid + u0 * 256;              // 0..1023 over both rows
        uint4 p = prow[u];
        float s = (u < 512) ? s0 : s1;
        int base = u * 8;
        wsm[base + 0] = (float)(((int)p.x & 15) - 8) * s;
        wsm[base + 1] = (float)((((int)p.x >> 4) & 15) - 8) * s;
        wsm[base + 2] = (float)(((int)p.y & 15) - 8) * s;
        wsm[base + 3] = (float)((((int)p.y >> 4) & 15) - 8) * s;
        wsm[base + 4] = (float)(((int)p.z & 15) - 8) * s;
        wsm[base + 5] = (float)((((int)p.z >> 4) & 15) - 8) * s;
        wsm[base + 6] = (float)(((int)p.w & 15) - 8) * s;
        wsm[base + 7] = (float)((((int)p.w >> 4) & 15) - 8) * s;
    }
    const int j0 = g_rowstart[row0];
    const int j1 = g_rowstart[row0 + 1];
    const int j2 = g_rowstart[row0 + 2];
    __syncthreads();

    for (int j = j0 + tid; j < j1; j += 256)
        atomicAdd(&wsm[cols[j]], vals[j]);
    for (int j = j1 + tid; j < j2; j += 256)
        atomicAdd(&wsm[IN_DIM + cols[j]], vals[j]);
    __syncthreads();

    uint4* orow = reinterpret_cast<uint4*>(g_Wh) + (size_t)row0 * 512;
    #pragma unroll
    for (int u0 = 0; u0 < 4; ++u0) {
        int u = tid + u0 * 256;
        int base = u * 8;
        uint4 o;
        o.x = h2_as_u32(__floats2half2_rn(wsm[base + 0], wsm[base + 1]));
        o.y = h2_as_u32(__floats2half2_rn(wsm[base + 2], wsm[base + 3]));
        o.z = h2_as_u32(__floats2half2_rn(wsm[base + 4], wsm[base + 5]));
        o.w = h2_as_u32(__floats2half2_rn(wsm[base + 6], wsm[base + 7]));
        orow[u] = o;
    }
}

// ---------------- GEMM: 4 warps, warp tile 64x64 (round-12 mainloop) ----------
// out = Xh * Wh^T. CTA tile 128x128, 4 warps (2x2), warp tile 64x64, K-tile 64
// (4 x k16 sub-steps), 3-stage cp.async pipeline (32KB/stage), 2 CTA/SM.
#define KTILE 64
#define A_BYTES 16384
#define STAGE_BYTES 32768
#define N_ITERS (IN_DIM / KTILE)   // 64

#define SWZ(r_, c_) ((r_) * 128 + ((((c_) ^ ((r_) & 7))) << 4))

__global__ void __launch_bounds__(128, 2) gemm_kernel(float* __restrict__ out) {
    extern __shared__ char smem[];
    const int tid  = threadIdx.x;
    const int lane = tid & 31;
    const int w    = tid >> 5;
    const int wm   = w & 1;        // 0..1 : 64-row half (M)
    const int wn   = w >> 1;       // 0..1 : 64-col half (N)
    const int mt   = blockIdx.x;   // 0..15
    const int nt   = blockIdx.y;   // 0..85

    float c[4][8][4];
    #pragma unroll
    for (int mi = 0; mi < 4; ++mi)
        #pragma unroll
        for (int ni = 0; ni < 8; ++ni)
            #pragma unroll
            for (int q = 0; q < 4; ++q) c[mi][ni][q] = 0.f;

    const int lr = tid >> 3;             // 0..15
    const int lc = tid & 7;              // chunk 0..7
    const unsigned sbase = smem_u32(smem);

    const int arow[4] = { wm * 64 +  0 + (lane & 15), wm * 64 + 16 + (lane & 15),
                          wm * 64 + 32 + (lane & 15), wm * 64 + 48 + (lane & 15) };
    const int acol = lane >> 4;                                   // 0..1
    const int brow[4] = { wn * 64 +  0 + (lane & 7) + ((lane >> 4) << 3),
                          wn * 64 + 16 + (lane & 7) + ((lane >> 4) << 3),
                          wn * 64 + 32 + (lane & 7) + ((lane >> 4) << 3),
                          wn * 64 + 48 + (lane & 7) + ((lane >> 4) << 3) };
    const int bcol = (lane >> 3) & 1;                             // 0..1

    const __half* Ab = g_Xh + (size_t)mt * 128 * IN_DIM;
    const __half* Bb = g_Wh + (size_t)nt * 128 * IN_DIM;

    #define LOAD_TILE(it_) do {                                                   \
        int k0_ = (it_) << 6;                                                     \
        unsigned sa_ = sbase + ((it_) % 3) * STAGE_BYTES;                         \
        unsigned sb_ = sa_ + A_BYTES;                                             \
        const __half* ap_ = Ab + k0_ + lc * 8;                                    \
        const __half* bp_ = Bb + k0_ + lc * 8;                                    \
        _Pragma("unroll")                                                         \
        for (int p_ = 0; p_ < 8; ++p_) {                                          \
            int r_ = lr + p_ * 16;                                                \
            CP16(sa_ + SWZ(r_, lc), ap_ + (size_t)r_ * IN_DIM);                   \
            CP16(sb_ + SWZ(r_, lc), bp_ + (size_t)r_ * IN_DIM);                   \
        }                                                                         \
    } while (0)

    #define LOAD_FRAGS(kk_, A_, B_) do {                                          \
        _Pragma("unroll")                                                         \
        for (int mi_ = 0; mi_ < 4; ++mi_)                                         \
            LDSM4((A_)[mi_], sa + SWZ(arow[mi_], 2 * (kk_) + acol));              \
        _Pragma("unroll")                                                         \
        for (int nj_ = 0; nj_ < 4; ++nj_)                                         \
            LDSM4((B_)[nj_], sb + SWZ(brow[nj_], 2 * (kk_) + bcol));              \
    } while (0)

    #define DO_MMAS(A_, B_) do {                                                  \
        _Pragma("unroll")                                                         \
        for (int mi_ = 0; mi_ < 4; ++mi_)                                         \
            _Pragma("unroll")                                                     \
            for (int ni_ = 0; ni_ < 8; ++ni_)                                     \
                MMA16816(c[mi_][ni_], (A_)[mi_],                                  \
                         (B_)[ni_ >> 1][(ni_ & 1) * 2 + 0],                       \
                         (B_)[ni_ >> 1][(ni_ & 1) * 2 + 1]);                      \
    } while (0)

    LOAD_TILE(0);
    asm volatile("cp.async.commit_group;" ::: "memory");
    LOAD_TILE(1);
    asm volatile("cp.async.commit_group;" ::: "memory");

    for (int it = 0; it < N_ITERS; ++it) {
        asm volatile("cp.async.wait_group 1;" ::: "memory");
        __syncthreads();

        unsigned sa = sbase + (it % 3) * STAGE_BYTES;
        unsigned sb = sa + A_BYTES;

        unsigned a[4][4], b[4][4];
        LOAD_FRAGS(0, a, b);

        if (it + 2 < N_ITERS) LOAD_TILE(it + 2);
        asm volatile("cp.async.commit_group;" ::: "memory");

        DO_MMAS(a, b);

        #pragma unroll
        for (int kk = 1; kk < 4; ++kk) {
            LOAD_FRAGS(kk, a, b);
            DO_MMAS(a, b);
        }
        // no trailing barrier: next iter's top barrier provides ordering
    }

    // ---- epilogue: direct fp32 stores ----
    const int r0 = mt * 128 + wm * 64 + (lane >> 2);
    const int c0 = nt * 128 + wn * 64 + (lane & 3) * 2;
    #pragma unroll
    for (int mi = 0; mi < 4; ++mi) {
        #pragma unroll
        for (int ni = 0; ni < 8; ++ni) {
            size_t rowA = (size_t)(r0 + mi * 16) * OUT_DIM + c0 + ni * 8;
            size_t rowB = rowA + (size_t)8 * OUT_DIM;
            float2 v01; v01.x = c[mi][ni][0]; v01.y = c[mi][ni][1];
            float2 v23; v23.x = c[mi][ni][2]; v23.y = c[mi][ni][3];
            *reinterpret_cast<float2*>(out + rowA) = v01;
            *reinterpret_cast<float2*>(out + rowB) = v23;
        }
    }
}

// ---------------- launcher ----------------
extern "C" void kernel_launch(void* const* d_in, const int* in_sizes, int n_in,
                              void* d_out, int out_size) {
    const float* x      = (const float*)d_in[0];
    const float* scales = (const float*)d_in[1];
    const float* vals   = (const float*)d_in[2];
    const int*   packed = (const int*)d_in[3];
    const int*   rows   = (const int*)d_in[4];
    const int*   cols   = (const int*)d_in[5];
    float* out = (float*)d_out;
    int nnz = in_sizes[2];

    // idempotent, non-stream API: safe under graph capture
    cudaFuncSetAttribute(gemm_kernel,
                         cudaFuncAttributeMaxDynamicSharedMemorySize,
                         3 * STAGE_BYTES);

    int rs_blks = (nnz + 255) / 256;
    prep0_kernel<<<rs_blks + XBLKS, 256>>>(rows, nnz, rs_blks, x);
    prep_kernel<<<OUT_DIM / 2, 256>>>(packed, scales, vals, cols);

    {
        dim3 grid(MTOK / 128, OUT_DIM / 128);  // (16, 86); x fastest -> B n-tile L2 reuse
        gemm_kernel<<<grid, 128, 3 * STAGE_BYTES>>>(out);
    }
}

// round 15
// speedup vs baseline: 1.0150x; 1.0150x over previous
#include <cuda_runtime.h>
#include <cuda_fp16.h>

#define OUT_DIM 11008
#define IN_DIM  4096
#define MTOK    2048

// ---------------- scratch (device globals; no runtime allocation) ----------------
__device__ __half g_Wh[(size_t)OUT_DIM * IN_DIM];
__device__ __half g_Xh[(size_t)MTOK * IN_DIM];
__device__ int    g_rowstart[OUT_DIM + 1];

static __device__ __forceinline__ unsigned smem_u32(const void* p) {
    return (unsigned)__cvta_generic_to_shared(p);
}

static __device__ __forceinline__ unsigned h2_as_u32(__half2 h) {
    return *reinterpret_cast<unsigned*>(&h);
}

#define CP16(dst_u32, src_ptr) \
    asm volatile("cp.async.cg.shared.global [%0], [%1], 16;" \
                 :: "r"(dst_u32), "l"(src_ptr) : "memory")

#define LDSM4(R, ADDR) \
    asm volatile("ldmatrix.sync.aligned.m8n8.x4.shared.b16 {%0,%1,%2,%3}, [%4];" \
                 : "=r"((R)[0]), "=r"((R)[1]), "=r"((R)[2]), "=r"((R)[3]) : "r"(ADDR))

#define MMA16816(C, A, B0, B1) \
    asm volatile("mma.sync.aligned.m16n8k16.row.col.f32.f16.f16.f32 " \
                 "{%0,%1,%2,%3}, {%4,%5,%6,%7}, {%8,%9}, {%0,%1,%2,%3};" \
                 : "+f"((C)[0]), "+f"((C)[1]), "+f"((C)[2]), "+f"((C)[3]) \
                 : "r"((A)[0]), "r"((A)[1]), "r"((A)[2]), "r"((A)[3]), \
                   "r"(B0), "r"(B1))

// streaming (evict-first) 64-bit store: output is write-once, never re-read
#define STG64_CS(ptr, v01) \
    asm volatile("st.global.cs.v2.f32 [%0], {%1, %2};" \
                 :: "l"(ptr), "f"((v01).x), "f"((v01).y) : "memory")

// ---------------- kernel 0: rowstart via boundary scatter ----------------
__global__ void rowstart_kernel(const int* __restrict__ rows, int nnz) {
    int i = blockIdx.x * blockDim.x + threadIdx.x;
    if (i >= nnz) return;
    int r  = rows[i];
    int rp = (i == 0) ? -1 : rows[i - 1];
    for (int q = rp + 1; q <= r; ++q) g_rowstart[q] = i;
    if (i == nnz - 1)
        for (int q = r + 1; q <= OUT_DIM; ++q) g_rowstart[q] = nnz;
}

// ---------------- fused prep kernel (round-12 structure) ----------------
// Blocks [0, OUT_DIM): one block per W row. Dequant row into fp32 smem,
// apply sparse entries (range from g_rowstart, smem fp32 atomics), write row
// once as fp16. Blocks [OUT_DIM, OUT_DIM + XBLKS): convert x fp32 -> fp16.
#define XBLKS 2048   // 2048 blocks * 512 units = 1048576 = MTOK*IN_DIM/8

__global__ void __launch_bounds__(256) prep_kernel(
        const int* __restrict__ packed, const float* __restrict__ scales,
        const float* __restrict__ vals, const int* __restrict__ cols,
        const float* __restrict__ x) {
    const int bid = blockIdx.x;
    const int tid = threadIdx.x;

    if (bid < OUT_DIM) {
        __shared__ float wsm[IN_DIM];
        const int row = bid;
        const float s = scales[row];
        const uint4* prow = reinterpret_cast<const uint4*>(packed) + (size_t)row * 512;

        #pragma unroll
        for (int u0 = 0; u0 < 2; ++u0) {
            int u = tid + u0 * 256;              // 0..511
            uint4 p = prow[u];
            int base = u * 8;
            wsm[base + 0] = (float)(((int)p.x & 15) - 8) * s;
            wsm[base + 1] = (float)((((int)p.x >> 4) & 15) - 8) * s;
            wsm[base + 2] = (float)(((int)p.y & 15) - 8) * s;
            wsm[base + 3] = (float)((((int)p.y >> 4) & 15) - 8) * s;
            wsm[base + 4] = (float)(((int)p.z & 15) - 8) * s;
            wsm[base + 5] = (float)((((int)p.z >> 4) & 15) - 8) * s;
            wsm[base + 6] = (float)(((int)p.w & 15) - 8) * s;
            wsm[base + 7] = (float)((((int)p.w >> 4) & 15) - 8) * s;
        }
        const int j0 = g_rowstart[row];
        const int j1 = g_rowstart[row + 1];
        __syncthreads();

        for (int j = j0 + tid; j < j1; j += 256)
            atomicAdd(&wsm[cols[j]], vals[j]);
        __syncthreads();

        uint4* orow = reinterpret_cast<uint4*>(g_Wh) + (size_t)row * 512;
        #pragma unroll
        for (int u0 = 0; u0 < 2; ++u0) {
            int u = tid + u0 * 256;
            int base = u * 8;
            uint4 o;
            o.x = h2_as_u32(__floats2half2_rn(wsm[base + 0], wsm[base + 1]));
            o.y = h2_as_u32(__floats2half2_rn(wsm[base + 2], wsm[base + 3]));
            o.z = h2_as_u32(__floats2half2_rn(wsm[base + 4], wsm[base + 5]));
            o.w = h2_as_u32(__floats2half2_rn(wsm[base + 6], wsm[base + 7]));
            orow[u] = o;
        }
    } else {
        // x convert: unit = 8 fp32 -> 8 fp16 (one uint4 out)
        size_t u = (size_t)(bid - OUT_DIM) * 512 + tid;
        #pragma unroll
        for (int q = 0; q < 2; ++q, u += 256) {
            float4 v0 = reinterpret_cast<const float4*>(x)[2 * u + 0];
            float4 v1 = reinterpret_cast<const float4*>(x)[2 * u + 1];
            uint4 o;
            o.x = h2_as_u32(__floats2half2_rn(v0.x, v0.y));
            o.y = h2_as_u32(__floats2half2_rn(v0.z, v0.w));
            o.z = h2_as_u32(__floats2half2_rn(v1.x, v1.y));
            o.w = h2_as_u32(__floats2half2_rn(v1.z, v1.w));
            reinterpret_cast<uint4*>(g_Xh)[u] = o;
        }
    }
}

// ---------------- GEMM: 4 warps, warp tile 64x64 (round-12 mainloop) ----------
// out = Xh * Wh^T. CTA tile 128x128, 4 warps (2x2), warp tile 64x64, K-tile 64
// (4 x k16 sub-steps), 3-stage cp.async pipeline (32KB/stage), 2 CTA/SM.
// Epilogue uses st.global.cs (evict-first): output is write-once, keep B/X
// tiles resident in L2.
#define KTILE 64
#define A_BYTES 16384
#define STAGE_BYTES 32768
#define N_ITERS (IN_DIM / KTILE)   // 64

#define SWZ(r_, c_) ((r_) * 128 + ((((c_) ^ ((r_) & 7))) << 4))

__global__ void __launch_bounds__(128, 2) gemm_kernel(float* __restrict__ out) {
    extern __shared__ char smem[];
    const int tid  = threadIdx.x;
    const int lane = tid & 31;
    const int w    = tid >> 5;
    const int wm   = w & 1;        // 0..1 : 64-row half (M)
    const int wn   = w >> 1;       // 0..1 : 64-col half (N)
    const int mt   = blockIdx.x;   // 0..15
    const int nt   = blockIdx.y;   // 0..85

    float c[4][8][4];
    #pragma unroll
    for (int mi = 0; mi < 4; ++mi)
        #pragma unroll
        for (int ni = 0; ni < 8; ++ni)
            #pragma unroll
            for (int q = 0; q < 4; ++q) c[mi][ni][q] = 0.f;

    const int lr = tid >> 3;             // 0..15
    const int lc = tid & 7;              // chunk 0..7
    const unsigned sbase = smem_u32(smem);

    const int arow[4] = { wm * 64 +  0 + (lane & 15), wm * 64 + 16 + (lane & 15),
                          wm * 64 + 32 + (lane & 15), wm * 64 + 48 + (lane & 15) };
    const int acol = lane >> 4;                                   // 0..1
    const int brow[4] = { wn * 64 +  0 + (lane & 7) + ((lane >> 4) << 3),
                          wn * 64 + 16 + (lane & 7) + ((lane >> 4) << 3),
                          wn * 64 + 32 + (lane & 7) + ((lane >> 4) << 3),
                          wn * 64 + 48 + (lane & 7) + ((lane >> 4) << 3) };
    const int bcol = (lane >> 3) & 1;                             // 0..1

    const __half* Ab = g_Xh + (size_t)mt * 128 * IN_DIM;
    const __half* Bb = g_Wh + (size_t)nt * 128 * IN_DIM;

    #define LOAD_TILE(it_) do {                                                   \
        int k0_ = (it_) << 6;                                                     \
        unsigned sa_ = sbase + ((it_) % 3) * STAGE_BYTES;                         \
        unsigned sb_ = sa_ + A_BYTES;                                             \
        const __half* ap_ = Ab + k0_ + lc * 8;                                    \
        const __half* bp_ = Bb + k0_ + lc * 8;                                    \
        _Pragma("unroll")                                                         \
        for (int p_ = 0; p_ < 8; ++p_) {                                          \
            int r_ = lr + p_ * 16;                                                \
            CP16(sa_ + SWZ(r_, lc), ap_ + (size_t)r_ * IN_DIM);                   \
            CP16(sb_ + SWZ(r_, lc), bp_ + (size_t)r_ * IN_DIM);                   \
        }                                                                         \
    } while (0)

    #define LOAD_FRAGS(kk_, A_, B_) do {                                          \
        _Pragma("unroll")                                                         \
        for (int mi_ = 0; mi_ < 4; ++mi_)                                         \
            LDSM4((A_)[mi_], sa + SWZ(arow[mi_], 2 * (kk_) + acol));              \
        _Pragma("unroll")                                                         \
        for (int nj_ = 0; nj_ < 4; ++nj_)                                         \
            LDSM4((B_)[nj_], sb + SWZ(brow[nj_], 2 * (kk_) + bcol));              \
    } while (0)

    #define DO_MMAS(A_, B_) do {                                                  \
        _Pragma("unroll")                                                         \
        for (int mi_ = 0; mi_ < 4; ++mi_)                                         \
            _Pragma("unroll")                                                     \
            for (int ni_ = 0; ni_ < 8; ++ni_)                                     \
                MMA16816(c[mi_][ni_], (A_)[mi_],                                  \
                         (B_)[ni_ >> 1][(ni_ & 1) * 2 + 0],                       \
                         (B_)[ni_ >> 1][(ni_ & 1) * 2 + 1]);                      \
    } while (0)

    LOAD_TILE(0);
    asm volatile("cp.async.commit_group;" ::: "memory");
    LOAD_TILE(1);
    asm volatile("cp.async.commit_group;" ::: "memory");

    for (int it = 0; it < N_ITERS; ++it) {
        asm volatile("cp.async.wait_group 1;" ::: "memory");
        __syncthreads();

        unsigned sa = sbase + (it % 3) * STAGE_BYTES;
        unsigned sb = sa + A_BYTES;

        unsigned a[4][4], b[4][4];
        LOAD_FRAGS(0, a, b);

        if (it + 2 < N_ITERS) LOAD_TILE(it + 2);
        asm volatile("cp.async.commit_group;" ::: "memory");

        DO_MMAS(a, b);

        #pragma unroll
        for (int kk = 1; kk < 4; ++kk) {
            LOAD_FRAGS(kk, a, b);
            DO_MMAS(a, b);
        }
        // no trailing barrier: next iter's top barrier provides ordering
    }

    // ---- epilogue: streaming fp32 stores (evict-first) ----
    const int r0 = mt * 128 + wm * 64 + (lane >> 2);
    const int c0 = nt * 128 + wn * 64 + (lane & 3) * 2;
    #pragma unroll
    for (int mi = 0; mi < 4; ++mi) {
        #pragma unroll
        for (int ni = 0; ni < 8; ++ni) {
            size_t rowA = (size_t)(r0 + mi * 16) * OUT_DIM + c0 + ni * 8;
            size_t rowB = rowA + (size_t)8 * OUT_DIM;
            float2 v01; v01.x = c[mi][ni][0]; v01.y = c[mi][ni][1];
            float2 v23; v23.x = c[mi][ni][2]; v23.y = c[mi][ni][3];
            STG64_CS(out + rowA, v01);
            STG64_CS(out + rowB, v23);
        }
    }
}

// ---------------- launcher ----------------
extern "C" void kernel_launch(void* const* d_in, const int* in_sizes, int n_in,
                              void* d_out, int out_size) {
    const float* x      = (const float*)d_in[0];
    const float* scales = (const float*)d_in[1];
    const float* vals   = (const float*)d_in[2];
    const int*   packed = (const int*)d_in[3];
    const int*   rows   = (const int*)d_in[4];
    const int*   cols   = (const int*)d_in[5];
    float* out = (float*)d_out;
    int nnz = in_sizes[2];

    // idempotent, non-stream API: safe under graph capture
    cudaFuncSetAttribute(gemm_kernel,
                         cudaFuncAttributeMaxDynamicSharedMemorySize,
                         3 * STAGE_BYTES);

    rowstart_kernel<<<(nnz + 255) / 256, 256>>>(rows, nnz);
    prep_kernel<<<OUT_DIM + XBLKS, 256>>>(packed, scales, vals, cols, x);

    {
        dim3 grid(MTOK / 128, OUT_DIM / 128);  // (16, 86); x fastest -> B n-tile L2 reuse
        gemm_kernel<<<grid, 128, 3 * STAGE_BYTES>>>(out);
    }
}